// round 7
// baseline (speedup 1.0000x reference)
#include <cuda_runtime.h>
#include <cuda_bf16.h>
#include <cstdint>

typedef uint32_t u32;

#define SQ 1024   // sequence length
#define CC 256    // QDIM == KDIM
#define EE 512    // EMBED
#define BB 8      // batch
#define HH 8      // heads
#define DD 64     // head dim

__device__ float g_Q[BB * EE * SQ];
__device__ float g_K[BB * EE * SQ];
__device__ float g_V[BB * EE * SQ];

// ---------------- helpers ----------------
__device__ __forceinline__ unsigned tf32c(float x) {
    unsigned r; asm("cvt.rna.tf32.f32 %0,%1;" : "=r"(r) : "f"(x)); return r;
}
__device__ __forceinline__ float tf32f(float x) { return __uint_as_float(tf32c(x)); }
__device__ __forceinline__ float ex2f(float x) {
    float r; asm("ex2.approx.ftz.f32 %0,%1;" : "=f"(r) : "f"(x)); return r;
}
__device__ __forceinline__ void mma_tf32(
    float& c0, float& c1, float& c2, float& c3,
    unsigned a0, unsigned a1, unsigned a2, unsigned a3,
    unsigned b0, unsigned b1)
{
    asm volatile(
        "mma.sync.aligned.m16n8k8.row.col.f32.tf32.tf32.f32 "
        "{%0,%1,%2,%3},{%4,%5,%6,%7},{%8,%9},{%0,%1,%2,%3};"
        : "+f"(c0), "+f"(c1), "+f"(c2), "+f"(c3)
        : "r"(a0), "r"(a1), "r"(a2), "r"(a3), "r"(b0), "r"(b1));
}
__device__ __forceinline__ void mma_bf16(
    float& c0, float& c1, float& c2, float& c3,
    u32 a0, u32 a1, u32 a2, u32 a3, u32 b0, u32 b1)
{
    asm volatile(
        "mma.sync.aligned.m16n8k16.row.col.f32.bf16.bf16.f32 "
        "{%0,%1,%2,%3},{%4,%5,%6,%7},{%8,%9},{%0,%1,%2,%3};"
        : "+f"(c0), "+f"(c1), "+f"(c2), "+f"(c3)
        : "r"(a0), "r"(a1), "r"(a2), "r"(a3), "r"(b0), "r"(b1));
}
__device__ __forceinline__ void ldsm4(u32& r0, u32& r1, u32& r2, u32& r3, u32 a) {
    asm volatile("ldmatrix.sync.aligned.m8n8.x4.shared.b16 {%0,%1,%2,%3},[%4];"
        : "=r"(r0), "=r"(r1), "=r"(r2), "=r"(r3) : "r"(a));
}
__device__ __forceinline__ u32 smem_u32(const void* p) {
    u32 a;
    asm("{ .reg .u64 t; cvta.to.shared.u64 t, %1; cvt.u32.u64 %0, t; }"
        : "=r"(a) : "l"(p));
    return a;
}
__device__ __forceinline__ u32 packh(__nv_bfloat16 a, __nv_bfloat16 b) {
    return (u32)__bfloat16_as_ushort(a) | ((u32)__bfloat16_as_ushort(b) << 16);
}
// split two floats into packed-hi and packed-lo bf16 words
__device__ __forceinline__ void split2(float x, float y, u32& h, u32& l) {
    __nv_bfloat16 hx = __float2bfloat16(x), hy = __float2bfloat16(y);
    __nv_bfloat16 lx = __float2bfloat16(x - __bfloat162float(hx));
    __nv_bfloat16 ly = __float2bfloat16(y - __bfloat162float(hy));
    h = packh(hx, hy); l = packh(lx, ly);
}

// ---------------------------------------------------------------------------
// Projection: Y[e][s] = W[e][c] X[c][s] + bias[e]   (tf32 mma, unchanged)
// ---------------------------------------------------------------------------
__global__ __launch_bounds__(256) void proj_kernel(
    const float* __restrict__ q_in, const float* __restrict__ k_in,
    const float* __restrict__ wq, const float* __restrict__ biasq,
    const float* __restrict__ wk, const float* __restrict__ biask,
    const float* __restrict__ wv, const float* __restrict__ biasv)
{
    const int z = blockIdx.z;
    const int b = z / 3;
    const int p = z % 3;
    const float* X    = (p == 0 ? q_in : k_in) + (size_t)b * CC * SQ;
    const float* W    = (p == 0) ? wq : (p == 1 ? wk : wv);
    const float* bias = (p == 0) ? biasq : (p == 1 ? biask : biasv);
    float* Y = (p == 0 ? g_Q : (p == 1 ? g_K : g_V)) + (size_t)b * EE * SQ;

    const int m0 = blockIdx.y * 128;
    const int n0 = blockIdx.x * 128;

    __shared__ __align__(16) float Ws[128 * 36];
    __shared__ __align__(16) float Xs[32 * 136];

    const int tid  = threadIdx.x;
    const int lane = tid & 31;
    const int wid  = tid >> 5;
    const int mw   = (wid & 1) * 64;
    const int nw   = (wid >> 1) * 32;
    const int r    = lane >> 2;
    const int l    = lane & 3;

    float c[4][4][4];
    #pragma unroll
    for (int mt = 0; mt < 4; mt++)
        #pragma unroll
        for (int nt = 0; nt < 4; nt++)
            #pragma unroll
            for (int e = 0; e < 4; e++) c[mt][nt][e] = 0.0f;

    for (int k0 = 0; k0 < CC; k0 += 32) {
        #pragma unroll
        for (int idx = tid; idx < 1024; idx += 256) {
            int row = idx >> 3, k4 = (idx & 7) * 4;
            float4 w4 = *(const float4*)(W + (size_t)(m0 + row) * CC + k0 + k4);
            float* ps = Ws + row * 36 + k4;
            ps[0] = tf32f(w4.x); ps[1] = tf32f(w4.y);
            ps[2] = tf32f(w4.z); ps[3] = tf32f(w4.w);
        }
        #pragma unroll
        for (int idx = tid; idx < 1024; idx += 256) {
            int k = idx >> 5, n4 = (idx & 31) * 4;
            float4 x4 = *(const float4*)(X + (size_t)(k0 + k) * SQ + n0 + n4);
            float* ps = Xs + k * 136 + n4;
            ps[0] = tf32f(x4.x); ps[1] = tf32f(x4.y);
            ps[2] = tf32f(x4.z); ps[3] = tf32f(x4.w);
        }
        __syncthreads();

        #pragma unroll
        for (int ks = 0; ks < 4; ks++) {
            unsigned a[4][4];
            #pragma unroll
            for (int mt = 0; mt < 4; mt++) {
                const float* ap = Ws + (mw + mt * 16 + r) * 36 + ks * 8 + l;
                a[mt][0] = __float_as_uint(ap[0]);
                a[mt][1] = __float_as_uint(ap[8 * 36]);
                a[mt][2] = __float_as_uint(ap[4]);
                a[mt][3] = __float_as_uint(ap[8 * 36 + 4]);
            }
            #pragma unroll
            for (int nt = 0; nt < 4; nt++) {
                const float* bp = Xs + (ks * 8 + l) * 136 + nw + nt * 8 + r;
                unsigned b0 = __float_as_uint(bp[0]);
                unsigned b1 = __float_as_uint(bp[4 * 136]);
                #pragma unroll
                for (int mt = 0; mt < 4; mt++)
                    mma_tf32(c[mt][nt][0], c[mt][nt][1], c[mt][nt][2], c[mt][nt][3],
                             a[mt][0], a[mt][1], a[mt][2], a[mt][3], b0, b1);
            }
        }
        __syncthreads();
    }

    #pragma unroll
    for (int mt = 0; mt < 4; mt++) {
        int e0 = m0 + mw + mt * 16 + r;
        float bv0 = __ldg(bias + e0);
        float bv1 = __ldg(bias + e0 + 8);
        #pragma unroll
        for (int nt = 0; nt < 4; nt++) {
            int s = n0 + nw + nt * 8 + 2 * l;
            *(float2*)(Y + (size_t)e0 * SQ + s) =
                make_float2(c[mt][nt][0] + bv0, c[mt][nt][1] + bv0);
            *(float2*)(Y + (size_t)(e0 + 8) * SQ + s) =
                make_float2(c[mt][nt][2] + bv1, c[mt][nt][3] + bv1);
        }
    }
}

// ---------------------------------------------------------------------------
// bf16-split flash attention with ldmatrix. Br=Bc=128, 256 thr, 8 warps x 16 rows.
// smem: hi/lo bf16 tiles. Q/K: [row 128][64 d] stride 144B. V: [64 d][128 j]
// stride 272B. P: [128 i][128 j] stride 272B. All ldsm phases conflict-free
// (row strides = 16B * odd -> banks 4t mod 32).
// ---------------------------------------------------------------------------
#define QROW 144
#define VROW 272
#define PROW 272
#define QH_O 0
#define QL_O 18432
#define KH_O 36864
#define KL_O 55296
#define VH_O 73728
#define VL_O 91136
#define PH_O 108544
#define PL_O 143360
#define ATTN_SMEM 178176

__global__ __launch_bounds__(256, 1) void attn_kernel(float* __restrict__ out)
{
    extern __shared__ char smc[];
    const u32 smb = smem_u32(smc);

    const int qb = 7 - (int)blockIdx.x;  // heavy blocks first
    const int h  = blockIdx.y;
    const int b  = blockIdx.z;

    const float* Qg = g_Q + ((size_t)b * EE + h * DD) * SQ;  // [d][s]
    const float* Kg = g_K + ((size_t)b * EE + h * DD) * SQ;
    const float* Vg = g_V + ((size_t)b * EE + h * DD) * SQ;
    float*       Og = out + ((size_t)b * EE + h * DD) * SQ;

    const int s0   = qb * 128;
    const int tid  = threadIdx.x;
    const int lane = tid & 31;
    const int wid  = tid >> 5;
    const int r    = lane >> 2;
    const int l    = lane & 3;
    const int ib   = wid * 16;

    const float qs = 0.125f * 1.4426950408889634f;  // 1/sqrt(64) * log2(e)

    // ---- stage Q once: transpose [d][s] -> [i][d] hi/lo bf16
    for (int mm = tid; mm < 512; mm += 256) {
        int dm = (mm & 15) * 4, im = (mm >> 4) * 4;
        float4 r0 = *(const float4*)(Qg + (size_t)(dm + 0) * SQ + s0 + im);
        float4 r1 = *(const float4*)(Qg + (size_t)(dm + 1) * SQ + s0 + im);
        float4 r2 = *(const float4*)(Qg + (size_t)(dm + 2) * SQ + s0 + im);
        float4 r3 = *(const float4*)(Qg + (size_t)(dm + 3) * SQ + s0 + im);
        float col[4][4] = {{r0.x, r1.x, r2.x, r3.x}, {r0.y, r1.y, r2.y, r3.y},
                           {r0.z, r1.z, r2.z, r3.z}, {r0.w, r1.w, r2.w, r3.w}};
        #pragma unroll
        for (int c2 = 0; c2 < 4; c2++) {
            int i = im + c2;
            u32 h0, l0, h1, l1;
            split2(col[c2][0] * qs, col[c2][1] * qs, h0, l0);
            split2(col[c2][2] * qs, col[c2][3] * qs, h1, l1);
            *(uint2*)(smc + QH_O + i * QROW + dm * 2) = make_uint2(h0, h1);
            *(uint2*)(smc + QL_O + i * QROW + dm * 2) = make_uint2(l0, l1);
        }
    }
    __syncthreads();

    // ---- preload Q A-fragments (loop-invariant): 4 k-steps x hi/lo
    u32 ah[4][4], al[4][4];
    {
        u32 rowb = (u32)(ib + (lane & 15)) * QROW;
        u32 koff = ((lane >> 4) & 1) * 16;   // bytes (8 bf16)
        #pragma unroll
        for (int kc = 0; kc < 4; kc++) {
            ldsm4(ah[kc][0], ah[kc][1], ah[kc][2], ah[kc][3],
                  smb + QH_O + rowb + kc * 32 + koff);
            ldsm4(al[kc][0], al[kc][1], al[kc][2], al[kc][3],
                  smb + QL_O + rowb + kc * 32 + koff);
        }
    }

    float o[8][4];
    #pragma unroll
    for (int nt = 0; nt < 8; nt++)
        #pragma unroll
        for (int e = 0; e < 4; e++) o[nt][e] = 0.0f;
    float m0r = -1e30f, m1r = -1e30f, l0r = 0.0f, l1r = 0.0f;

    for (int kb = 0; kb <= qb; kb++) {
        __syncthreads();   // prev PV reads of V/K done
        const int c0 = kb * 128;

        // ---- stage K: transpose [d][j] -> [j][d] hi/lo
        for (int mm = tid; mm < 512; mm += 256) {
            int dm = (mm & 15) * 4, jm = (mm >> 4) * 4;
            float4 r0 = *(const float4*)(Kg + (size_t)(dm + 0) * SQ + c0 + jm);
            float4 r1 = *(const float4*)(Kg + (size_t)(dm + 1) * SQ + c0 + jm);
            float4 r2 = *(const float4*)(Kg + (size_t)(dm + 2) * SQ + c0 + jm);
            float4 r3 = *(const float4*)(Kg + (size_t)(dm + 3) * SQ + c0 + jm);
            float col[4][4] = {{r0.x, r1.x, r2.x, r3.x}, {r0.y, r1.y, r2.y, r3.y},
                               {r0.z, r1.z, r2.z, r3.z}, {r0.w, r1.w, r2.w, r3.w}};
            #pragma unroll
            for (int c2 = 0; c2 < 4; c2++) {
                int j = jm + c2;
                u32 h0, l0, h1, l1;
                split2(col[c2][0], col[c2][1], h0, l0);
                split2(col[c2][2], col[c2][3], h1, l1);
                *(uint2*)(smc + KH_O + j * QROW + dm * 2) = make_uint2(h0, h1);
                *(uint2*)(smc + KL_O + j * QROW + dm * 2) = make_uint2(l0, l1);
            }
        }
        // ---- stage V: natural [d][j] hi/lo
        {
            int d = tid >> 2, jq = (tid & 3) * 32;
            #pragma unroll
            for (int g = 0; g < 8; g++) {
                int j4 = jq + g * 4;
                float4 v4 = *(const float4*)(Vg + (size_t)d * SQ + c0 + j4);
                u32 h0, l0, h1, l1;
                split2(v4.x, v4.y, h0, l0);
                split2(v4.z, v4.w, h1, l1);
                *(uint2*)(smc + VH_O + d * VROW + j4 * 2) = make_uint2(h0, h1);
                *(uint2*)(smc + VL_O + d * VROW + j4 * 2) = make_uint2(l0, l1);
            }
        }
        __syncthreads();

        // ---- QK^T: 16 rows x 128 cols per warp; terms hh + lh + hl
        float sc[16][4];
        #pragma unroll
        for (int nt = 0; nt < 16; nt++)
            #pragma unroll
            for (int e = 0; e < 4; e++) sc[nt][e] = 0.0f;

        {
            u32 jrow = ((u32)(lane & 7) + (((u32)lane >> 4) & 1) * 8) * QROW;
            u32 koff = (((u32)lane >> 3) & 1) * 16;
            #pragma unroll
            for (int ntp = 0; ntp < 8; ntp++) {
                u32 base = (u32)ntp * (16 * QROW) + jrow + koff;
                #pragma unroll
                for (int kc = 0; kc < 4; kc++) {
                    u32 bh0, bh1, bh2, bh3, bl0, bl1, bl2, bl3;
                    ldsm4(bh0, bh1, bh2, bh3, smb + KH_O + base + kc * 32);
                    mma_bf16(sc[2*ntp][0], sc[2*ntp][1], sc[2*ntp][2], sc[2*ntp][3],
                             ah[kc][0], ah[kc][1], ah[kc][2], ah[kc][3], bh0, bh1);
                    mma_bf16(sc[2*ntp+1][0], sc[2*ntp+1][1], sc[2*ntp+1][2], sc[2*ntp+1][3],
                             ah[kc][0], ah[kc][1], ah[kc][2], ah[kc][3], bh2, bh3);
                    mma_bf16(sc[2*ntp][0], sc[2*ntp][1], sc[2*ntp][2], sc[2*ntp][3],
                             al[kc][0], al[kc][1], al[kc][2], al[kc][3], bh0, bh1);
                    mma_bf16(sc[2*ntp+1][0], sc[2*ntp+1][1], sc[2*ntp+1][2], sc[2*ntp+1][3],
                             al[kc][0], al[kc][1], al[kc][2], al[kc][3], bh2, bh3);
                    ldsm4(bl0, bl1, bl2, bl3, smb + KL_O + base + kc * 32);
                    mma_bf16(sc[2*ntp][0], sc[2*ntp][1], sc[2*ntp][2], sc[2*ntp][3],
                             ah[kc][0], ah[kc][1], ah[kc][2], ah[kc][3], bl0, bl1);
                    mma_bf16(sc[2*ntp+1][0], sc[2*ntp+1][1], sc[2*ntp+1][2], sc[2*ntp+1][3],
                             ah[kc][0], ah[kc][1], ah[kc][2], ah[kc][3], bl2, bl3);
                }
            }
        }

        // ---- causal mask on the diagonal block
        if (kb == qb) {
            const int il0 = s0 + ib + r, il1 = il0 + 8;
            #pragma unroll
            for (int nt = 0; nt < 16; nt++) {
                int j = c0 + nt * 8 + 2 * l;
                if (j     > il0) sc[nt][0] = -1e30f;
                if (j + 1 > il0) sc[nt][1] = -1e30f;
                if (j     > il1) sc[nt][2] = -1e30f;
                if (j + 1 > il1) sc[nt][3] = -1e30f;
            }
        }

        // ---- online softmax (rows live in a quad: shfl xor 1,2)
        float mx0 = -1e30f, mx1 = -1e30f;
        #pragma unroll
        for (int nt = 0; nt < 16; nt++) {
            mx0 = fmaxf(mx0, fmaxf(sc[nt][0], sc[nt][1]));
            mx1 = fmaxf(mx1, fmaxf(sc[nt][2], sc[nt][3]));
        }
        mx0 = fmaxf(mx0, __shfl_xor_sync(0xffffffffu, mx0, 1));
        mx0 = fmaxf(mx0, __shfl_xor_sync(0xffffffffu, mx0, 2));
        mx1 = fmaxf(mx1, __shfl_xor_sync(0xffffffffu, mx1, 1));
        mx1 = fmaxf(mx1, __shfl_xor_sync(0xffffffffu, mx1, 2));
        float mn0 = fmaxf(m0r, mx0), mn1 = fmaxf(m1r, mx1);
        float corr0 = ex2f(m0r - mn0), corr1 = ex2f(m1r - mn1);
        m0r = mn0; m1r = mn1;

        float rs0 = 0.0f, rs1 = 0.0f;
        #pragma unroll
        for (int nt = 0; nt < 16; nt++) {
            sc[nt][0] = ex2f(sc[nt][0] - mn0); rs0 += sc[nt][0];
            sc[nt][1] = ex2f(sc[nt][1] - mn0); rs0 += sc[nt][1];
            sc[nt][2] = ex2f(sc[nt][2] - mn1); rs1 += sc[nt][2];
            sc[nt][3] = ex2f(sc[nt][3] - mn1); rs1 += sc[nt][3];
        }
        rs0 += __shfl_xor_sync(0xffffffffu, rs0, 1);
        rs0 += __shfl_xor_sync(0xffffffffu, rs0, 2);
        rs1 += __shfl_xor_sync(0xffffffffu, rs1, 1);
        rs1 += __shfl_xor_sync(0xffffffffu, rs1, 2);
        l0r = l0r * corr0 + rs0;
        l1r = l1r * corr1 + rs1;

        // ---- P -> smem bf16 hi/lo (warp-local rows)
        #pragma unroll
        for (int nt = 0; nt < 16; nt++) {
            int jo = (nt * 8 + 2 * l) * 2;   // byte offset within row
            u32 h0, lo0, h1, lo1;
            split2(sc[nt][0], sc[nt][1], h0, lo0);
            split2(sc[nt][2], sc[nt][3], h1, lo1);
            *(u32*)(smc + PH_O + (ib + r) * PROW + jo)     = h0;
            *(u32*)(smc + PL_O + (ib + r) * PROW + jo)     = lo0;
            *(u32*)(smc + PH_O + (ib + r + 8) * PROW + jo) = h1;
            *(u32*)(smc + PL_O + (ib + r + 8) * PROW + jo) = lo1;
        }
        __syncwarp();

        // ---- rescale O accumulators
        #pragma unroll
        for (int nt = 0; nt < 8; nt++) {
            o[nt][0] *= corr0; o[nt][1] *= corr0;
            o[nt][2] *= corr1; o[nt][3] *= corr1;
        }

        // ---- PV: 16 rows x 64 d per warp; terms PhVh + PlVh + PhVl
        {
            u32 prow = (u32)(ib + (lane & 15)) * PROW + (((u32)lane >> 4) & 1) * 16;
            u32 vrow = ((u32)(lane & 7) + (((u32)lane >> 4) & 1) * 8) * VROW;
            u32 vkof = (((u32)lane >> 3) & 1) * 16;
            #pragma unroll
            for (int kc2 = 0; kc2 < 8; kc2++) {
                u32 aph0, aph1, aph2, aph3, apl0, apl1, apl2, apl3;
                ldsm4(aph0, aph1, aph2, aph3, smb + PH_O + prow + kc2 * 32);
                ldsm4(apl0, apl1, apl2, apl3, smb + PL_O + prow + kc2 * 32);
                u32 vko = (u32)kc2 * 32 + vkof;
                #pragma unroll
                for (int dtp = 0; dtp < 4; dtp++) {
                    u32 vb = (u32)dtp * (16 * VROW) + vrow + vko;
                    u32 bh0, bh1, bh2, bh3, bl0, bl1, bl2, bl3;
                    ldsm4(bh0, bh1, bh2, bh3, smb + VH_O + vb);
                    mma_bf16(o[2*dtp][0], o[2*dtp][1], o[2*dtp][2], o[2*dtp][3],
                             aph0, aph1, aph2, aph3, bh0, bh1);
                    mma_bf16(o[2*dtp+1][0], o[2*dtp+1][1], o[2*dtp+1][2], o[2*dtp+1][3],
                             aph0, aph1, aph2, aph3, bh2, bh3);
                    mma_bf16(o[2*dtp][0], o[2*dtp][1], o[2*dtp][2], o[2*dtp][3],
                             apl0, apl1, apl2, apl3, bh0, bh1);
                    mma_bf16(o[2*dtp+1][0], o[2*dtp+1][1], o[2*dtp+1][2], o[2*dtp+1][3],
                             apl0, apl1, apl2, apl3, bh2, bh3);
                    ldsm4(bl0, bl1, bl2, bl3, smb + VL_O + vb);
                    mma_bf16(o[2*dtp][0], o[2*dtp][1], o[2*dtp][2], o[2*dtp][3],
                             aph0, aph1, aph2, aph3, bl0, bl1);
                    mma_bf16(o[2*dtp+1][0], o[2*dtp+1][1], o[2*dtp+1][2], o[2*dtp+1][3],
                             aph0, aph1, aph2, aph3, bl2, bl3);
                }
            }
        }
    }

    // ---- epilogue: normalize, stage O [i][d] (stride PROW bytes = 68 floats)
    float inv0 = 1.0f / l0r, inv1 = 1.0f / l1r;
    #pragma unroll
    for (int nt = 0; nt < 8; nt++) {
        int d = nt * 8 + 2 * l;
        float* p0 = (float*)(smc + PH_O + (ib + r) * PROW) + d;
        float* p1 = (float*)(smc + PH_O + (ib + r + 8) * PROW) + d;
        p0[0] = o[nt][0] * inv0; p0[1] = o[nt][1] * inv0;
        p1[0] = o[nt][2] * inv1; p1[1] = o[nt][3] * inv1;
    }
    __syncthreads();
    {
        const int dcol = tid & 63;
        const int ibk  = tid >> 6;
        #pragma unroll
        for (int g = 0; g < 8; g++) {
            int i4 = ibk * 32 + g * 4;
            float4 w;
            w.x = ((const float*)(smc + PH_O + (i4 + 0) * PROW))[dcol];
            w.y = ((const float*)(smc + PH_O + (i4 + 1) * PROW))[dcol];
            w.z = ((const float*)(smc + PH_O + (i4 + 2) * PROW))[dcol];
            w.w = ((const float*)(smc + PH_O + (i4 + 3) * PROW))[dcol];
            *(float4*)(Og + (size_t)dcol * SQ + s0 + i4) = w;
        }
    }
}

// ---------------------------------------------------------------------------
extern "C" void kernel_launch(void* const* d_in, const int* in_sizes, int n_in,
                              void* d_out, int out_size)
{
    const float* query = (const float*)d_in[0];
    const float* key   = (const float*)d_in[1];
    const float* Wq    = (const float*)d_in[2];
    const float* bq    = (const float*)d_in[3];
    const float* Wk    = (const float*)d_in[4];
    const float* bk    = (const float*)d_in[5];
    const float* Wv    = (const float*)d_in[6];
    const float* bv    = (const float*)d_in[7];

    dim3 g1(SQ / 128, EE / 128, BB * 3);
    proj_kernel<<<g1, 256>>>(query, key, Wq, bq, Wk, bk, Wv, bv);

    cudaFuncSetAttribute(attn_kernel,
                         cudaFuncAttributeMaxDynamicSharedMemorySize, ATTN_SMEM);
    dim3 g2(8, HH, BB);
    attn_kernel<<<g2, 256, ATTN_SMEM>>>((float*)d_out);
}

// round 10
// speedup vs baseline: 1.5242x; 1.5242x over previous
#include <cuda_runtime.h>
#include <cstdint>

typedef uint32_t u32;

#define SQ 1024   // sequence length
#define CC 256    // QDIM == KDIM
#define EE 512    // EMBED
#define BB 8      // batch
#define HH 8      // heads
#define DD 64     // head dim

__device__ float g_Q[BB * EE * SQ];
__device__ float g_K[BB * EE * SQ];
__device__ float g_V[BB * EE * SQ];

__device__ __forceinline__ unsigned tf32c(float x) {
    unsigned r; asm("cvt.rna.tf32.f32 %0,%1;" : "=r"(r) : "f"(x)); return r;
}
__device__ __forceinline__ float tf32f(float x) { return __uint_as_float(tf32c(x)); }
__device__ __forceinline__ float ex2f(float x) {
    float r; asm("ex2.approx.ftz.f32 %0,%1;" : "=f"(r) : "f"(x)); return r;
}
__device__ __forceinline__ void mma_tf32(
    float& c0, float& c1, float& c2, float& c3,
    unsigned a0, unsigned a1, unsigned a2, unsigned a3,
    unsigned b0, unsigned b1)
{
    asm volatile(
        "mma.sync.aligned.m16n8k8.row.col.f32.tf32.tf32.f32 "
        "{%0,%1,%2,%3},{%4,%5,%6,%7},{%8,%9},{%0,%1,%2,%3};"
        : "+f"(c0), "+f"(c1), "+f"(c2), "+f"(c3)
        : "r"(a0), "r"(a1), "r"(a2), "r"(a3), "r"(b0), "r"(b1));
}
__device__ __forceinline__ u32 smem_u32(const void* p) {
    u32 a;
    asm("{ .reg .u64 t; cvta.to.shared.u64 t, %1; cvt.u32.u64 %0, t; }"
        : "=r"(a) : "l"(p));
    return a;
}
__device__ __forceinline__ void cpa16(u32 dst, const void* src) {
    asm volatile("cp.async.cg.shared.global [%0], [%1], 16;"
                 :: "r"(dst), "l"(src) : "memory");
}
#define CP_COMMIT() asm volatile("cp.async.commit_group;" ::: "memory")
#define CP_WAIT(n)  asm volatile("cp.async.wait_group %0;" :: "n"(n) : "memory")

// ---------------------------------------------------------------------------
// Projection: Y[e][s] = tf32(W[e][c] X[c][s] + bias[e])  [Q additionally
// pre-scaled by 1/sqrt(64)*log2(e)].  CTA 128x128, BK=32, tf32 mma.
// ---------------------------------------------------------------------------
__global__ __launch_bounds__(256) void proj_kernel(
    const float* __restrict__ q_in, const float* __restrict__ k_in,
    const float* __restrict__ wq, const float* __restrict__ biasq,
    const float* __restrict__ wk, const float* __restrict__ biask,
    const float* __restrict__ wv, const float* __restrict__ biasv)
{
    const int z = blockIdx.z;
    const int b = z / 3;
    const int p = z % 3;
    const float* X    = (p == 0 ? q_in : k_in) + (size_t)b * CC * SQ;
    const float* W    = (p == 0) ? wq : (p == 1 ? wk : wv);
    const float* bias = (p == 0) ? biasq : (p == 1 ? biask : biasv);
    float* Y = (p == 0 ? g_Q : (p == 1 ? g_K : g_V)) + (size_t)b * EE * SQ;
    const float oscale = (p == 0) ? 0.125f * 1.4426950408889634f : 1.0f;

    const int m0 = blockIdx.y * 128;
    const int n0 = blockIdx.x * 128;

    __shared__ __align__(16) float Ws[128 * 36];
    __shared__ __align__(16) float Xs[32 * 136];

    const int tid  = threadIdx.x;
    const int lane = tid & 31;
    const int wid  = tid >> 5;
    const int mw   = (wid & 1) * 64;
    const int nw   = (wid >> 1) * 32;
    const int r    = lane >> 2;
    const int l    = lane & 3;

    float c[4][4][4];
    #pragma unroll
    for (int mt = 0; mt < 4; mt++)
        #pragma unroll
        for (int nt = 0; nt < 4; nt++)
            #pragma unroll
            for (int e = 0; e < 4; e++) c[mt][nt][e] = 0.0f;

    for (int k0 = 0; k0 < CC; k0 += 32) {
        #pragma unroll
        for (int idx = tid; idx < 1024; idx += 256) {
            int row = idx >> 3, k4 = (idx & 7) * 4;
            float4 w4 = *(const float4*)(W + (size_t)(m0 + row) * CC + k0 + k4);
            float* ps = Ws + row * 36 + k4;
            ps[0] = tf32f(w4.x); ps[1] = tf32f(w4.y);
            ps[2] = tf32f(w4.z); ps[3] = tf32f(w4.w);
        }
        #pragma unroll
        for (int idx = tid; idx < 1024; idx += 256) {
            int k = idx >> 5, n4 = (idx & 31) * 4;
            float4 x4 = *(const float4*)(X + (size_t)(k0 + k) * SQ + n0 + n4);
            float* ps = Xs + k * 136 + n4;
            ps[0] = tf32f(x4.x); ps[1] = tf32f(x4.y);
            ps[2] = tf32f(x4.z); ps[3] = tf32f(x4.w);
        }
        __syncthreads();

        #pragma unroll
        for (int ks = 0; ks < 4; ks++) {
            unsigned a[4][4];
            #pragma unroll
            for (int mt = 0; mt < 4; mt++) {
                const float* ap = Ws + (mw + mt * 16 + r) * 36 + ks * 8 + l;
                a[mt][0] = __float_as_uint(ap[0]);
                a[mt][1] = __float_as_uint(ap[8 * 36]);
                a[mt][2] = __float_as_uint(ap[4]);
                a[mt][3] = __float_as_uint(ap[8 * 36 + 4]);
            }
            #pragma unroll
            for (int nt = 0; nt < 4; nt++) {
                const float* bp = Xs + (ks * 8 + l) * 136 + nw + nt * 8 + r;
                unsigned b0 = __float_as_uint(bp[0]);
                unsigned b1 = __float_as_uint(bp[4 * 136]);
                #pragma unroll
                for (int mt = 0; mt < 4; mt++)
                    mma_tf32(c[mt][nt][0], c[mt][nt][1], c[mt][nt][2], c[mt][nt][3],
                             a[mt][0], a[mt][1], a[mt][2], a[mt][3], b0, b1);
            }
        }
        __syncthreads();
    }

    #pragma unroll
    for (int mt = 0; mt < 4; mt++) {
        int e0 = m0 + mw + mt * 16 + r;
        float bv0 = __ldg(bias + e0);
        float bv1 = __ldg(bias + e0 + 8);
        #pragma unroll
        for (int nt = 0; nt < 4; nt++) {
            int s = n0 + nw + nt * 8 + 2 * l;
            *(float2*)(Y + (size_t)e0 * SQ + s) =
                make_float2(tf32f((c[mt][nt][0] + bv0) * oscale),
                            tf32f((c[mt][nt][1] + bv0) * oscale));
            *(float2*)(Y + (size_t)(e0 + 8) * SQ + s) =
                make_float2(tf32f((c[mt][nt][2] + bv1) * oscale),
                            tf32f((c[mt][nt][3] + bv1) * oscale));
        }
    }
}

// ---------------------------------------------------------------------------
// Causal flash attention, tf32 mma, cp.async pipelined staging.
// Br=Bc=128, 256 threads, 8 warps x 16 query rows (math identical to R3).
// K double-buffered; V single-buffered (issued at iter top, used at PV).
// Smem (floats): Qs[64][136] | Ks0[64][136] | Ks1[64][136] | Vs[64][132]
//                | Ps[128][132]  -> 201 KB.
// ---------------------------------------------------------------------------
#define QKP 136
#define VPP 132
#define QS_F 0
#define KS_F 8704
#define VS_F 26112
#define PS_F 34560

__global__ __launch_bounds__(256, 1) void attn_kernel(float* __restrict__ out)
{
    extern __shared__ float smf[];
    const u32 smb = smem_u32(smf);
    float* Qs = smf + QS_F;
    float* Vs = smf + VS_F;
    float* Ps = smf + PS_F;

    const int qb = 7 - (int)blockIdx.x;  // heavy blocks first
    const int h  = blockIdx.y;
    const int b  = blockIdx.z;

    const float* Qg = g_Q + ((size_t)b * EE + h * DD) * SQ;  // [d][s], tf32+scaled
    const float* Kg = g_K + ((size_t)b * EE + h * DD) * SQ;
    const float* Vg = g_V + ((size_t)b * EE + h * DD) * SQ;
    float*       Og = out + ((size_t)b * EE + h * DD) * SQ;

    const int s0   = qb * 128;
    const int tid  = threadIdx.x;
    const int lane = tid & 31;
    const int wid  = tid >> 5;
    const int r    = lane >> 2;
    const int l    = lane & 3;
    const int ib   = wid * 16;

    // raw tile copy: 64 rows x 128 floats, 8x 16B chunks per thread
    auto stage = [&](int base_f, int rowstride_f, const float* gsrc) {
        #pragma unroll
        for (int k2 = 0; k2 < 8; k2++) {
            int cch = tid + k2 * 256;
            int d = cch >> 5, o16 = cch & 31;
            u32 dst = smb + (u32)(base_f + d * rowstride_f + o16 * 4) * 4u;
            cpa16(dst, gsrc + (size_t)d * SQ + o16 * 4);
        }
    };

    // ---- prologue: Q + K(0) in one group
    stage(QS_F, QKP, Qg + s0);
    stage(KS_F, QKP, Kg);        // c0 = 0
    CP_COMMIT();

    float o[8][4];
    #pragma unroll
    for (int nt = 0; nt < 8; nt++)
        #pragma unroll
        for (int e = 0; e < 4; e++) o[nt][e] = 0.0f;
    float m0r = -1e30f, m1r = -1e30f, l0r = 0.0f, l1r = 0.0f;

    for (int kb = 0; kb <= qb; kb++) {
        const int c0 = kb * 128;
        __syncthreads();   // prev iter PV reads of Vs / Ks[(kb+1)&1] done

        // ---- issue V(kb), then K(kb+1)
        stage(VS_F, VPP, Vg + c0);
        CP_COMMIT();
        if (kb < qb) {
            stage(KS_F + ((kb + 1) & 1) * 8704, QKP, Kg + c0 + 128);
            CP_COMMIT();
        }
        // wait for K(kb) (+Q on the first iteration)
        if (kb == 0) { CP_WAIT(1); } else { CP_WAIT(2); }
        __syncthreads();

        const float* Ks = smf + KS_F + (kb & 1) * 8704;

        // ---- QK^T: 16 rows x 128 cols per warp
        float sc[16][4];
        #pragma unroll
        for (int nt = 0; nt < 16; nt++)
            #pragma unroll
            for (int e = 0; e < 4; e++) sc[nt][e] = 0.0f;

        #pragma unroll
        for (int ks = 0; ks < 8; ks++) {
            const float* ap = Qs + (ks * 8 + l) * QKP + ib + r;
            unsigned a0 = __float_as_uint(ap[0]);
            unsigned a1 = __float_as_uint(ap[8]);
            unsigned a2 = __float_as_uint(ap[4 * QKP]);
            unsigned a3 = __float_as_uint(ap[4 * QKP + 8]);
            #pragma unroll
            for (int nt = 0; nt < 16; nt++) {
                const float* bp = Ks + (ks * 8 + l) * QKP + nt * 8 + r;
                unsigned b0 = __float_as_uint(bp[0]);
                unsigned b1 = __float_as_uint(bp[4 * QKP]);
                mma_tf32(sc[nt][0], sc[nt][1], sc[nt][2], sc[nt][3],
                         a0, a1, a2, a3, b0, b1);
            }
        }

        // ---- causal mask on the diagonal block
        if (kb == qb) {
            const int il0 = s0 + ib + r, il1 = il0 + 8;
            #pragma unroll
            for (int nt = 0; nt < 16; nt++) {
                int j = c0 + nt * 8 + 2 * l;
                if (j     > il0) sc[nt][0] = -1e30f;
                if (j + 1 > il0) sc[nt][1] = -1e30f;
                if (j     > il1) sc[nt][2] = -1e30f;
                if (j + 1 > il1) sc[nt][3] = -1e30f;
            }
        }

        // ---- online softmax (rows live in a quad: shfl xor 1,2)
        float mx0 = -1e30f, mx1 = -1e30f;
        #pragma unroll
        for (int nt = 0; nt < 16; nt++) {
            mx0 = fmaxf(mx0, fmaxf(sc[nt][0], sc[nt][1]));
            mx1 = fmaxf(mx1, fmaxf(sc[nt][2], sc[nt][3]));
        }
        mx0 = fmaxf(mx0, __shfl_xor_sync(0xffffffffu, mx0, 1));
        mx0 = fmaxf(mx0, __shfl_xor_sync(0xffffffffu, mx0, 2));
        mx1 = fmaxf(mx1, __shfl_xor_sync(0xffffffffu, mx1, 1));
        mx1 = fmaxf(mx1, __shfl_xor_sync(0xffffffffu, mx1, 2));
        float mn0 = fmaxf(m0r, mx0), mn1 = fmaxf(m1r, mx1);
        float corr0 = ex2f(m0r - mn0), corr1 = ex2f(m1r - mn1);
        m0r = mn0; m1r = mn1;

        float rs0 = 0.0f, rs1 = 0.0f;
        #pragma unroll
        for (int nt = 0; nt < 16; nt++) {
            sc[nt][0] = ex2f(sc[nt][0] - mn0); rs0 += sc[nt][0];
            sc[nt][1] = ex2f(sc[nt][1] - mn0); rs0 += sc[nt][1];
            sc[nt][2] = ex2f(sc[nt][2] - mn1); rs1 += sc[nt][2];
            sc[nt][3] = ex2f(sc[nt][3] - mn1); rs1 += sc[nt][3];
        }
        rs0 += __shfl_xor_sync(0xffffffffu, rs0, 1);
        rs0 += __shfl_xor_sync(0xffffffffu, rs0, 2);
        rs1 += __shfl_xor_sync(0xffffffffu, rs1, 1);
        rs1 += __shfl_xor_sync(0xffffffffu, rs1, 2);
        l0r = l0r * corr0 + rs0;
        l1r = l1r * corr1 + rs1;

        // ---- P -> smem (tf32), warp-local rows
        #pragma unroll
        for (int nt = 0; nt < 16; nt++) {
            int jo = nt * 8 + 2 * l;
            *(float2*)(Ps + (ib + r) * VPP + jo) =
                make_float2(tf32f(sc[nt][0]), tf32f(sc[nt][1]));
            *(float2*)(Ps + (ib + r + 8) * VPP + jo) =
                make_float2(tf32f(sc[nt][2]), tf32f(sc[nt][3]));
        }
        __syncwarp();

        // ---- rescale O accumulators
        #pragma unroll
        for (int nt = 0; nt < 8; nt++) {
            o[nt][0] *= corr0; o[nt][1] *= corr0;
            o[nt][2] *= corr1; o[nt][3] *= corr1;
        }

        // ---- wait V(kb) (and K(kb+1)), then PV
        CP_WAIT(0);
        __syncthreads();

        #pragma unroll
        for (int ks = 0; ks < 16; ks++) {
            const float* ap = Ps + (ib + r) * VPP + ks * 8 + l;
            unsigned a0 = __float_as_uint(ap[0]);
            unsigned a1 = __float_as_uint(ap[8 * VPP]);
            unsigned a2 = __float_as_uint(ap[4]);
            unsigned a3 = __float_as_uint(ap[8 * VPP + 4]);
            #pragma unroll
            for (int nt = 0; nt < 8; nt++) {
                const float* bp = Vs + (nt * 8 + r) * VPP + ks * 8 + l;
                unsigned b0 = __float_as_uint(bp[0]);
                unsigned b1 = __float_as_uint(bp[4]);
                mma_tf32(o[nt][0], o[nt][1], o[nt][2], o[nt][3],
                         a0, a1, a2, a3, b0, b1);
            }
        }
    }

    // ---- epilogue: normalize, stage O as [i][d] (pad 68) in Ps, coalesced STG
    float inv0 = 1.0f / l0r, inv1 = 1.0f / l1r;
    __syncthreads();
    #pragma unroll
    for (int nt = 0; nt < 8; nt++) {
        int d = nt * 8 + 2 * l;
        float* p0 = Ps + (ib + r) * 68 + d;
        float* p1 = Ps + (ib + r + 8) * 68 + d;
        p0[0] = o[nt][0] * inv0; p0[1] = o[nt][1] * inv0;
        p1[0] = o[nt][2] * inv1; p1[1] = o[nt][3] * inv1;
    }
    __syncthreads();

    const int dcol = tid & 63;
    const int ibk  = tid >> 6;
    #pragma unroll
    for (int g = 0; g < 8; g++) {
        int i4 = ibk * 32 + g * 4;
        float4 w;
        w.x = Ps[(i4 + 0) * 68 + dcol];
        w.y = Ps[(i4 + 1) * 68 + dcol];
        w.z = Ps[(i4 + 2) * 68 + dcol];
        w.w = Ps[(i4 + 3) * 68 + dcol];
        *(float4*)(Og + (size_t)dcol * SQ + s0 + i4) = w;
    }
}

// ---------------------------------------------------------------------------
extern "C" void kernel_launch(void* const* d_in, const int* in_sizes, int n_in,
                              void* d_out, int out_size)
{
    const float* query = (const float*)d_in[0];
    const float* key   = (const float*)d_in[1];
    const float* Wq    = (const float*)d_in[2];
    const float* bq    = (const float*)d_in[3];
    const float* Wk    = (const float*)d_in[4];
    const float* bk    = (const float*)d_in[5];
    const float* Wv    = (const float*)d_in[6];
    const float* bv    = (const float*)d_in[7];

    dim3 g1(SQ / 128, EE / 128, BB * 3);
    proj_kernel<<<g1, 256>>>(query, key, Wq, bq, Wk, bk, Wv, bv);

    const int attn_smem = (PS_F + 128 * VPP) * 4;  // 205,824 B
    cudaFuncSetAttribute(attn_kernel,
                         cudaFuncAttributeMaxDynamicSharedMemorySize, attn_smem);
    dim3 g2(8, HH, BB);
    attn_kernel<<<g2, 256, attn_smem>>>((float*)d_out);
}